// round 9
// baseline (speedup 1.0000x reference)
#include <cuda_runtime.h>
#include <cstdint>

// ---------------------------------------------------------------------------
// Problem constants
// ---------------------------------------------------------------------------
constexpr int NTOK = 8192;
constexpr int DIM  = 1024;
constexpr int HID  = 4096;
constexpr int NE   = 8;
constexpr int NC   = 8;
constexpr int NCAP = 8192;

// GEMM tile config
constexpr int BM = 128, BN = 128, BK = 32;
constexpr int A_STR = 40;                       // f32 words; LDS.64 conflict-free
constexpr int B_STR = 132;                      // f32 words
constexpr int A_TILE_B = BM * A_STR * 4;        // 20480
constexpr int B_TILE_B = BK * B_STR * 4;        // 16896
constexpr int SMEM_BYTES = 2 * (A_TILE_B + B_TILE_B);  // 74752 (<= 2 CTAs/SM)

// ---------------------------------------------------------------------------
// Device scratch
// ---------------------------------------------------------------------------
__device__ float g_pre[(size_t)NTOK * DIM];
__device__ float g_hidden[(size_t)NTOK * DIM];
__device__ float g_h1[(size_t)2 * NTOK * HID];
__device__ float g_contrib[(size_t)2 * NTOK * DIM];
__device__ float g_final[(size_t)NTOK * DIM];
__device__ int   g_cnt[NE];
__device__ int   g_off[NE];
__device__ int   g_list[NE * NCAP];
__device__ int   g_tokslot[NE * NCAP];
__device__ float g_gatev[NE * NCAP];

// ---------------------------------------------------------------------------
// Helpers
// ---------------------------------------------------------------------------
__device__ __forceinline__ uint32_t smem_u32(const void* p) {
    uint32_t a;
    asm("{ .reg .u64 t; cvta.to.shared.u64 t, %1; cvt.u32.u64 %0, t; }" : "=r"(a) : "l"(p));
    return a;
}

__device__ __forceinline__ void cp16(uint32_t dst, const void* src, bool pred) {
    int sz = pred ? 16 : 0;
    asm volatile("cp.async.cg.shared.global [%0], [%1], 16, %2;\n"
                 :: "r"(dst), "l"(src), "r"(sz));
}
#define CP_COMMIT() asm volatile("cp.async.commit_group;\n" ::: "memory")
#define CP_WAIT(n)  asm volatile("cp.async.wait_group %0;\n" :: "n"(n) : "memory")

// Pack 2 floats into bf16x2 (lo half = x0, hi half = x1); residual pair -> lo.
__device__ __forceinline__ uint32_t pack_split(float x0, float x1, uint32_t& lo) {
    uint32_t h;
    asm("cvt.rn.bf16x2.f32 %0, %1, %2;" : "=r"(h) : "f"(x1), "f"(x0));
    float h0 = __uint_as_float(h << 16);
    float h1 = __uint_as_float(h & 0xFFFF0000u);
    asm("cvt.rn.bf16x2.f32 %0, %1, %2;" : "=r"(lo) : "f"(x1 - h1), "f"(x0 - h0));
    return h;
}

__device__ __forceinline__ void mma_bf16(float* d, const uint32_t* a, const uint32_t* b) {
    asm volatile(
        "mma.sync.aligned.m16n8k16.row.col.f32.bf16.bf16.f32 "
        "{%0,%1,%2,%3}, {%4,%5,%6,%7}, {%8,%9}, {%0,%1,%2,%3};\n"
        : "+f"(d[0]), "+f"(d[1]), "+f"(d[2]), "+f"(d[3])
        : "r"(a[0]), "r"(a[1]), "r"(a[2]), "r"(a[3]), "r"(b[0]), "r"(b[1]));
}

__device__ __forceinline__ float gelu_t(float x) {
    return 0.5f * x * (1.f + tanhf(0.7978845608028654f * (x + 0.044715f * x * x * x)));
}

__device__ __forceinline__ void row_stats1024(float s, float q, float& mu, float& rstd) {
    __shared__ float shs[8], shq[8];
    #pragma unroll
    for (int o = 16; o; o >>= 1) {
        s += __shfl_xor_sync(0xffffffffu, s, o);
        q += __shfl_xor_sync(0xffffffffu, q, o);
    }
    int w = threadIdx.x >> 5;
    __syncthreads();
    if ((threadIdx.x & 31) == 0) { shs[w] = s; shq[w] = q; }
    __syncthreads();
    float ts = 0.f, tq = 0.f;
    #pragma unroll
    for (int k = 0; k < 8; k++) { ts += shs[k]; tq += shq[k]; }
    mu = ts * (1.f / DIM);
    float var = tq * (1.f / DIM) - mu * mu;
    rstd = rsqrtf(var + 1e-5f);
}

// ---------------------------------------------------------------------------
// Core tiled GEMM, 3x bf16 compensation, cp.async double-buffered, 2 CTAs/SM.
//  smem: A [m][k] f32 stride 40, B [k][n] f32 stride 132.
// ---------------------------------------------------------------------------
template <int MODE>
__global__ void __launch_bounds__(256, 2)
gemm_tpl(const float* __restrict__ A, const float* __restrict__ Bmat,
         const float* __restrict__ bias, int K, int Nw, int ldA) {
    extern __shared__ float smem[];
    float* sAf = smem;                               // 2 x A_TILE_B
    float* sBf = smem + 2 * (A_TILE_B / 4);          // 2 x B_TILE_B
    const uint32_t sA_addr = smem_u32(sAf);
    const uint32_t sB_addr = smem_u32(sBf);

    const int e = blockIdx.z;
    int M;
    const float* Ap;
    const int* ridx = nullptr;
    int obase = 0;
    if (MODE == 0) {
        M = NTOK; Ap = A;
    } else if (MODE == 1) {
        M = g_cnt[e]; Ap = g_hidden; ridx = g_list + e * NCAP; obase = g_off[e];
    } else {
        M = g_cnt[e]; Ap = g_h1 + (size_t)g_off[e] * HID;
    }
    if ((int)blockIdx.y * BM >= M) return;

    const float* Bp    = Bmat + (size_t)e * K * Nw;
    const float* biasP = bias + (size_t)e * Nw;

    const int tid  = threadIdx.x;
    const int lane = tid & 31, warp = tid >> 5;
    const int wm = warp & 1, wn = warp >> 1;
    const int g = lane >> 2, c = lane & 3;
    const int mBase = blockIdx.y * BM;
    const int nBase = blockIdx.x * BN;

    // cp.async assignments
    const int am   = tid & 127;           // A row within tile
    const int ahalf = tid >> 7;           // 0/1: k-halves of 16 floats
    const int mg = mBase + am;
    const bool aval = mg < M;
    int grow = mg;
    if (MODE == 1 && aval) grow = ridx[mg];
    const float* aRow = Ap + (size_t)(aval ? grow : 0) * ldA + ahalf * 16;
    const uint32_t aDstBase = sA_addr + am * (A_STR * 4) + ahalf * 64;

    const int bk = tid >> 3;              // B k-row within tile
    const int bn = tid & 7;               // 16-float n group
    const float* bRow = Bp + (size_t)bk * Nw + nBase + bn * 16;
    const uint32_t bDstBase = sB_addr + bk * (B_STR * 4) + bn * 64;

    auto ISSUE = [&](int kt) {
        const int buf = kt & 1;
        const float* as = aRow + kt * BK;
        uint32_t ad = aDstBase + buf * A_TILE_B;
        #pragma unroll
        for (int q = 0; q < 4; q++) cp16(ad + q * 16, as + q * 4, aval);
        const float* bs = bRow + (size_t)kt * BK * Nw;
        uint32_t bd = bDstBase + buf * B_TILE_B;
        #pragma unroll
        for (int q = 0; q < 4; q++) cp16(bd + q * 16, bs + q * 4, true);
    };

    float acc[4][4][4];
    #pragma unroll
    for (int i = 0; i < 4; i++)
        #pragma unroll
        for (int j = 0; j < 4; j++)
            #pragma unroll
            for (int k = 0; k < 4; k++) acc[i][j][k] = 0.f;

    const int nkt = K / BK;
    ISSUE(0);
    CP_COMMIT();

    for (int kt = 0; kt < nkt; kt++) {
        if (kt + 1 < nkt) {
            ISSUE(kt + 1);
            CP_COMMIT();
            CP_WAIT(1);
        } else {
            CP_WAIT(0);
        }
        __syncthreads();

        const int buf = kt & 1;
        const float* aT = sAf + buf * (A_TILE_B / 4);
        const float* bT = sBf + buf * (B_TILE_B / 4);
        #pragma unroll
        for (int ks = 0; ks < 2; ks++) {
            const int k0 = ks * 16 + c * 2;
            uint32_t ah[4][4], al[4][4];
            #pragma unroll
            for (int i = 0; i < 4; i++) {
                const int m = wm * 64 + i * 16 + g;
                float2 v0 = *reinterpret_cast<const float2*>(aT + m * A_STR + k0);
                float2 v1 = *reinterpret_cast<const float2*>(aT + (m + 8) * A_STR + k0);
                float2 v2 = *reinterpret_cast<const float2*>(aT + m * A_STR + k0 + 8);
                float2 v3 = *reinterpret_cast<const float2*>(aT + (m + 8) * A_STR + k0 + 8);
                ah[i][0] = pack_split(v0.x, v0.y, al[i][0]);
                ah[i][1] = pack_split(v1.x, v1.y, al[i][1]);
                ah[i][2] = pack_split(v2.x, v2.y, al[i][2]);
                ah[i][3] = pack_split(v3.x, v3.y, al[i][3]);
            }
            #pragma unroll
            for (int j = 0; j < 4; j++) {
                const int n = wn * 32 + j * 8 + g;
                float b00 = bT[(k0 + 0) * B_STR + n];
                float b01 = bT[(k0 + 1) * B_STR + n];
                float b10 = bT[(k0 + 8) * B_STR + n];
                float b11 = bT[(k0 + 9) * B_STR + n];
                uint32_t bh[2], bl[2];
                bh[0] = pack_split(b00, b01, bl[0]);
                bh[1] = pack_split(b10, b11, bl[1]);
                #pragma unroll
                for (int i = 0; i < 4; i++) {
                    mma_bf16(acc[i][j], al[i], bh);
                    mma_bf16(acc[i][j], ah[i], bl);
                    mma_bf16(acc[i][j], ah[i], bh);
                }
            }
        }
        __syncthreads();
    }

    // Epilogue (D frag layout unchanged)
    #pragma unroll
    for (int i = 0; i < 4; i++) {
        int r0 = mBase + wm * 64 + i * 16 + g;
        int r1 = r0 + 8;
        #pragma unroll
        for (int j = 0; j < 4; j++) {
            int col = nBase + wn * 32 + j * 8 + 2 * c;
            float2 bv = *reinterpret_cast<const float2*>(biasP + col);
            float v00 = acc[i][j][0] + bv.x;
            float v01 = acc[i][j][1] + bv.y;
            float v10 = acc[i][j][2] + bv.x;
            float v11 = acc[i][j][3] + bv.y;
            if (MODE == 0) {
                *reinterpret_cast<float2*>(g_pre + (size_t)r0 * DIM + col) = make_float2(v00, v01);
                *reinterpret_cast<float2*>(g_pre + (size_t)r1 * DIM + col) = make_float2(v10, v11);
            } else if (MODE == 1) {
                if (r0 < M)
                    *reinterpret_cast<float2*>(g_h1 + (size_t)(obase + r0) * HID + col) =
                        make_float2(gelu_t(v00), gelu_t(v01));
                if (r1 < M)
                    *reinterpret_cast<float2*>(g_h1 + (size_t)(obase + r1) * HID + col) =
                        make_float2(gelu_t(v10), gelu_t(v11));
            } else {
                if (r0 < M) {
                    float gt = g_gatev[e * NCAP + r0];
                    int dst  = g_tokslot[e * NCAP + r0];
                    *reinterpret_cast<float2*>(g_contrib + (size_t)dst * DIM + col) =
                        make_float2(v00 * gt, v01 * gt);
                }
                if (r1 < M) {
                    float gt = g_gatev[e * NCAP + r1];
                    int dst  = g_tokslot[e * NCAP + r1];
                    *reinterpret_cast<float2*>(g_contrib + (size_t)dst * DIM + col) =
                        make_float2(v10 * gt, v11 * gt);
                }
            }
        }
    }
}

// ---------------------------------------------------------------------------
// LayerNorm of g_pre -> g_hidden
// ---------------------------------------------------------------------------
__global__ void __launch_bounds__(256) ln1_k(const float* __restrict__ gw,
                                             const float* __restrict__ bw) {
    int row = blockIdx.x, t = threadIdx.x;
    float4 v = reinterpret_cast<const float4*>(g_pre + (size_t)row * DIM)[t];
    float s = v.x + v.y + v.z + v.w;
    float q = v.x * v.x + v.y * v.y + v.z * v.z + v.w * v.w;
    float mu, rs;
    row_stats1024(s, q, mu, rs);
    float4 gg = reinterpret_cast<const float4*>(gw)[t];
    float4 bb = reinterpret_cast<const float4*>(bw)[t];
    float4 o;
    o.x = (v.x - mu) * rs * gg.x + bb.x;
    o.y = (v.y - mu) * rs * gg.y + bb.y;
    o.z = (v.z - mu) * rs * gg.z + bb.z;
    o.w = (v.w - mu) * rs * gg.w + bb.w;
    reinterpret_cast<float4*>(g_hidden + (size_t)row * DIM)[t] = o;
}

// ---------------------------------------------------------------------------
// Router
// ---------------------------------------------------------------------------
__global__ void __launch_bounds__(256) router_k(const float* __restrict__ Wg) {
    int tok  = blockIdx.x * 8 + (threadIdx.x >> 5);
    int lane = threadIdx.x & 31;
    const float4* h4 = reinterpret_cast<const float4*>(g_hidden + (size_t)tok * DIM);
    float a[8];
    #pragma unroll
    for (int ci = 0; ci < 8; ci++) a[ci] = 0.f;
    for (int t = lane; t < DIM / 4; t += 32) {
        float4 h = h4[t];
        const float* wr = Wg + (size_t)t * 4 * NE;
        #pragma unroll
        for (int u = 0; u < 4; u++) {
            float hv = (u == 0) ? h.x : (u == 1) ? h.y : (u == 2) ? h.z : h.w;
            float4 w0 = reinterpret_cast<const float4*>(wr + u * NE)[0];
            float4 w1 = reinterpret_cast<const float4*>(wr + u * NE)[1];
            a[0] += hv * w0.x; a[1] += hv * w0.y; a[2] += hv * w0.z; a[3] += hv * w0.w;
            a[4] += hv * w1.x; a[5] += hv * w1.y; a[6] += hv * w1.z; a[7] += hv * w1.w;
        }
    }
    #pragma unroll
    for (int ci = 0; ci < 8; ci++)
        #pragma unroll
        for (int o = 16; o; o >>= 1) a[ci] += __shfl_xor_sync(0xffffffffu, a[ci], o);
    if (lane == 0) {
        int bi = 0; float bv = a[0];
        #pragma unroll
        for (int ci = 1; ci < 8; ci++) if (a[ci] > bv) { bv = a[ci]; bi = ci; }
        int si = -1; float sv = -3.4e38f;
        #pragma unroll
        for (int ci = 0; ci < 8; ci++)
            if (ci != bi && a[ci] > sv) { sv = a[ci]; si = ci; }
        if (si < 0) si = (bi + 1) & 7;
        float p0 = 1.f / (1.f + expf(sv - bv));
        float p1 = 1.f - p0;
        int pos = atomicAdd(&g_cnt[bi], 1);
        g_list[bi * NCAP + pos] = tok;
        g_gatev[bi * NCAP + pos] = p0;
        g_tokslot[bi * NCAP + pos] = tok * 2;
        pos = atomicAdd(&g_cnt[si], 1);
        g_list[si * NCAP + pos] = tok;
        g_gatev[si * NCAP + pos] = p1;
        g_tokslot[si * NCAP + pos] = tok * 2 + 1;
    }
}

__global__ void zero_k() {
    if (threadIdx.x < NE) g_cnt[threadIdx.x] = 0;
}

__global__ void scan_k() {
    if (threadIdx.x == 0) {
        int s = 0;
        for (int e = 0; e < NE; e++) { g_off[e] = s; s += g_cnt[e]; }
    }
}

// ---------------------------------------------------------------------------
// Combine + double LN
// ---------------------------------------------------------------------------
__global__ void __launch_bounds__(256) combine_k(const float* __restrict__ gm,
                                                 const float* __restrict__ bm,
                                                 const float* __restrict__ go,
                                                 const float* __restrict__ bo) {
    int row = blockIdx.x, t = threadIdx.x;
    float4 v  = reinterpret_cast<const float4*>(g_hidden + (size_t)row * DIM)[t];
    float4 c0 = reinterpret_cast<const float4*>(g_contrib + (size_t)(2 * row) * DIM)[t];
    float4 c1 = reinterpret_cast<const float4*>(g_contrib + (size_t)(2 * row + 1) * DIM)[t];
    v.x += c0.x + c1.x; v.y += c0.y + c1.y; v.z += c0.z + c1.z; v.w += c0.w + c1.w;
    float s = v.x + v.y + v.z + v.w;
    float q = v.x * v.x + v.y * v.y + v.z * v.z + v.w * v.w;
    float mu, rs;
    row_stats1024(s, q, mu, rs);
    float4 g1 = reinterpret_cast<const float4*>(gm)[t];
    float4 b1 = reinterpret_cast<const float4*>(bm)[t];
    float4 y;
    y.x = (v.x - mu) * rs * g1.x + b1.x;
    y.y = (v.y - mu) * rs * g1.y + b1.y;
    y.z = (v.z - mu) * rs * g1.z + b1.z;
    y.w = (v.w - mu) * rs * g1.w + b1.w;
    s = y.x + y.y + y.z + y.w;
    q = y.x * y.x + y.y * y.y + y.z * y.z + y.w * y.w;
    float mu2, rs2;
    row_stats1024(s, q, mu2, rs2);
    float4 g2 = reinterpret_cast<const float4*>(go)[t];
    float4 b2 = reinterpret_cast<const float4*>(bo)[t];
    float4 o;
    o.x = (y.x - mu2) * rs2 * g2.x + b2.x;
    o.y = (y.y - mu2) * rs2 * g2.y + b2.y;
    o.z = (y.z - mu2) * rs2 * g2.z + b2.z;
    o.w = (y.w - mu2) * rs2 * g2.w + b2.w;
    reinterpret_cast<float4*>(g_final + (size_t)row * DIM)[t] = o;
}

// ---------------------------------------------------------------------------
// Classifier
// ---------------------------------------------------------------------------
__global__ void __launch_bounds__(256) cls_k(const float* __restrict__ Wc,
                                             const float* __restrict__ bc,
                                             float* __restrict__ out) {
    int tok  = blockIdx.x * 8 + (threadIdx.x >> 5);
    int lane = threadIdx.x & 31;
    const float4* h4 = reinterpret_cast<const float4*>(g_final + (size_t)tok * DIM);
    float a[8];
    #pragma unroll
    for (int ci = 0; ci < 8; ci++) a[ci] = 0.f;
    for (int t = lane; t < DIM / 4; t += 32) {
        float4 h = h4[t];
        const float* wr = Wc + (size_t)t * 4 * NC;
        #pragma unroll
        for (int u = 0; u < 4; u++) {
            float hv = (u == 0) ? h.x : (u == 1) ? h.y : (u == 2) ? h.z : h.w;
            float4 w0 = reinterpret_cast<const float4*>(wr + u * NC)[0];
            float4 w1 = reinterpret_cast<const float4*>(wr + u * NC)[1];
            a[0] += hv * w0.x; a[1] += hv * w0.y; a[2] += hv * w0.z; a[3] += hv * w0.w;
            a[4] += hv * w1.x; a[5] += hv * w1.y; a[6] += hv * w1.z; a[7] += hv * w1.w;
        }
    }
    #pragma unroll
    for (int ci = 0; ci < 8; ci++)
        #pragma unroll
        for (int o = 16; o; o >>= 1) a[ci] += __shfl_xor_sync(0xffffffffu, a[ci], o);
    if (lane == 0) {
        #pragma unroll
        for (int ci = 0; ci < 8; ci++)
            out[(size_t)tok * NC + ci] = a[ci] + bc[ci];
    }
}

// ---------------------------------------------------------------------------
// Entry point
// ---------------------------------------------------------------------------
extern "C" void kernel_launch(void* const* d_in, const int* in_sizes, int n_in,
                              void* d_out, int out_size) {
    (void)in_sizes; (void)n_in; (void)out_size;
    const float* x    = (const float*)d_in[0];
    const float* Wp   = (const float*)d_in[1];
    const float* bp   = (const float*)d_in[2];
    const float* gin  = (const float*)d_in[3];
    const float* bin  = (const float*)d_in[4];
    const float* Wg   = (const float*)d_in[5];
    const float* W1   = (const float*)d_in[6];
    const float* b1   = (const float*)d_in[7];
    const float* W2   = (const float*)d_in[8];
    const float* b2   = (const float*)d_in[9];
    const float* gmoe = (const float*)d_in[10];
    const float* bmoe = (const float*)d_in[11];
    const float* gout = (const float*)d_in[12];
    const float* bout = (const float*)d_in[13];
    const float* Wc   = (const float*)d_in[14];
    const float* bc   = (const float*)d_in[15];
    float* out = (float*)d_out;

    cudaFuncSetAttribute((const void*)gemm_tpl<0>,
                         cudaFuncAttributeMaxDynamicSharedMemorySize, SMEM_BYTES);
    cudaFuncSetAttribute((const void*)gemm_tpl<1>,
                         cudaFuncAttributeMaxDynamicSharedMemorySize, SMEM_BYTES);
    cudaFuncSetAttribute((const void*)gemm_tpl<2>,
                         cudaFuncAttributeMaxDynamicSharedMemorySize, SMEM_BYTES);

    gemm_tpl<0><<<dim3(DIM / BN, NTOK / BM, 1), 256, SMEM_BYTES>>>(x, Wp, bp, DIM, DIM, DIM);
    ln1_k<<<NTOK, 256>>>(gin, bin);
    zero_k<<<1, 32>>>();
    router_k<<<NTOK / 8, 256>>>(Wg);
    scan_k<<<1, 32>>>();
    gemm_tpl<1><<<dim3(HID / BN, NTOK / BM, NE), 256, SMEM_BYTES>>>(nullptr, W1, b1, DIM, HID, DIM);
    gemm_tpl<2><<<dim3(DIM / BN, NTOK / BM, NE), 256, SMEM_BYTES>>>(nullptr, W2, b2, HID, DIM, HID);
    combine_k<<<NTOK, 256>>>(gmoe, bmoe, gout, bout);
    cls_k<<<NTOK / 8, 256>>>(Wc, bc, out);
}